// round 15
// baseline (speedup 1.0000x reference)
#include <cuda_runtime.h>
#include <cuda_fp16.h>
#include <mma.h>
#include <cstdint>

using namespace nvcuda;

// ---------------- problem constants ----------------
#define BB 4
#define SS 4096
#define DD 1024
#define MROWS (BB*SS)        // 16384
#define NPROJ 6144           // q|k|v|ar|ai|g
#define CHUNKS 64
#define CLEN 64
#define EPS 1e-6f

#define OFF_Q  0
#define OFF_K  1024
#define OFF_V  2048
#define OFF_AR 3072
#define OFF_AI 4096
#define OFF_G  5120

// ---------------- GEMM tiling (fp16 operands, fp32 accum) ----------------
#define BM 128
#define BN 128
#define BK 32                // halfs per K chunk
#define KITERS (DD/BK)       // 32
#define LDA_S 40             // padded A row stride (halfs)
#define LDB_S 136            // padded B row stride (halfs)
#define ASTAGE (BM*LDA_S)    // 5120 halfs
#define BSTAGE (BK*LDB_S)    // 4352 halfs
#define NSTAGE 4
#define SMEM_BYTES (NSTAGE*(ASTAGE+BSTAGE)*2)   // 75776 B

// ---------------- scratch (device globals) ----------------
__device__ __half g_xnh[(size_t)MROWS * DD];      // 32 MB
__device__ float  g_proj[(size_t)MROWS * NPROJ];  // 384 MB
__device__ __half g_yh[(size_t)MROWS * DD];       // 32 MB
__device__ __half g_wr[(size_t)DD * NPROJ];       // fused weights fp16 [1024,6144]
__device__ __half g_wro[(size_t)DD * DD];
__device__ float g_cAr[BB * CHUNKS * DD];
__device__ float g_cAi[BB * CHUNKS * DD];
__device__ float g_cHr[BB * CHUNKS * DD];
__device__ float g_cHi[BB * CHUNKS * DD];
__device__ float g_hinr[BB * CHUNKS * DD];
__device__ float g_hini[BB * CHUNKS * DD];

// ---------------- helpers ----------------
__device__ __forceinline__ uint32_t smem_u32(const void* p) {
    uint32_t a;
    asm("{ .reg .u64 t; cvta.to.shared.u64 t, %1; cvt.u32.u64 %0, t; }" : "=r"(a) : "l"(p));
    return a;
}
__device__ __forceinline__ void cp16(void* dst, const void* src) {
    uint32_t d = smem_u32(dst);
    asm volatile("cp.async.cg.shared.global [%0], [%1], 16;" :: "r"(d), "l"(src));
}
#define CP_COMMIT() asm volatile("cp.async.commit_group;" ::: "memory")
#define CP_WAIT2()  asm volatile("cp.async.wait_group 2;" ::: "memory")

__device__ __forceinline__ uint2 f4_to_h4(float4 v) {
    __half2 lo = __floats2half2_rn(v.x, v.y);
    __half2 hi = __floats2half2_rn(v.z, v.w);
    uint2 r;
    r.x = *(uint32_t*)&lo;
    r.y = *(uint32_t*)&hi;
    return r;
}

// ---------------- RMSNorm: x -> g_xnh (half) ----------------
__global__ void __launch_bounds__(256) rmsnorm_kernel(const float* __restrict__ x,
                                                      const float* __restrict__ scale) {
    int row = blockIdx.x;
    int tid = threadIdx.x;
    const float4* xr = (const float4*)(x + (size_t)row * DD);
    float4 v = xr[tid];
    float ss = v.x * v.x + v.y * v.y + v.z * v.z + v.w * v.w;
    #pragma unroll
    for (int o = 16; o; o >>= 1) ss += __shfl_xor_sync(0xffffffffu, ss, o);
    __shared__ float sbuf[8];
    if ((tid & 31) == 0) sbuf[tid >> 5] = ss;
    __syncthreads();
    if (tid < 8) {
        float t = sbuf[tid];
        #pragma unroll
        for (int o = 4; o; o >>= 1) t += __shfl_xor_sync(0xffu, t, o);
        if (tid == 0) sbuf[0] = t;
    }
    __syncthreads();
    float inv = rsqrtf(sbuf[0] * (1.0f / DD) + EPS);
    float4 sc = ((const float4*)scale)[tid];
    float4 o;
    o.x = v.x * inv * sc.x;
    o.y = v.y * inv * sc.y;
    o.z = v.z * inv * sc.z;
    o.w = v.w * inv * sc.w;
    *(uint2*)(g_xnh + (size_t)row * DD + tid * 4) = f4_to_h4(o);
}

// ---------------- weight converts ----------------
__global__ void __launch_bounds__(256) w3_to_half(const float4* __restrict__ q,
                                                  const float4* __restrict__ k,
                                                  const float4* __restrict__ v) {
    int row = blockIdx.x;
    int tid = threadIdx.x;
    const float4* srcs[3] = { q, k, v };
    #pragma unroll
    for (int m = 0; m < 3; m++) {
        float4 val = srcs[m][(size_t)row * 256 + tid];
        *(uint2*)(g_wr + (size_t)row * NPROJ + m * 1024 + tid * 4) = f4_to_h4(val);
    }
}
__global__ void __launch_bounds__(256) wrest_to_half(const float4* __restrict__ wa,
                                                     const float4* __restrict__ wg,
                                                     const float4* __restrict__ wo) {
    int bid = blockIdx.x;
    int tid = threadIdx.x;
    if (bid < 2048) {               // wa: 1024 rows x 512 f4
        int k = bid >> 1;
        int c = (bid & 1) * 256 + tid;
        float4 v = wa[(size_t)k * 512 + c];
        *(uint2*)(g_wr + (size_t)k * NPROJ + 3072 + c * 4) = f4_to_h4(v);
    } else if (bid < 3072) {        // wg
        int k = bid - 2048;
        float4 v = wg[(size_t)k * 256 + tid];
        *(uint2*)(g_wr + (size_t)k * NPROJ + 5120 + tid * 4) = f4_to_h4(v);
    } else {                        // wo
        int k = bid - 3072;
        float4 v = wo[(size_t)k * 256 + tid];
        *(uint2*)(g_wro + (size_t)k * DD + tid * 4) = f4_to_h4(v);
    }
}

// ---------------- fp16 GEMM (256 thr, 4x2 warps, 4-stage cp.async, M-swizzled raster) ----------------
__global__ void __launch_bounds__(256, 2) gemm_fp16(const __half* __restrict__ A,
                                                    const __half* __restrict__ W,
                                                    float* __restrict__ C, int ldwc) {
    extern __shared__ __half sm[];
    __half* Abase = sm;
    __half* Bbase = sm + NSTAGE * ASTAGE;

    int tid = threadIdx.x;
    int wid = tid >> 5;
    int wm = wid & 3;            // 4 warps along M (32 rows each)
    int wn = wid >> 2;           // 2 warps along N (64 cols each)

    // CTA raster swizzle: groups of 8 M-tiles share N sweeps (L2 locality).
    int lin = blockIdx.y * gridDim.x + blockIdx.x;
    int grp = lin >> 3;            // gridDim.y is a multiple of 8
    int mi  = (grp % (gridDim.y >> 3)) * 8 + (lin & 7);
    int ni  = grp / (gridDim.y >> 3);
    int m0 = mi * BM;
    int n0 = ni * BN;

    const __half* Ap = A + (size_t)m0 * DD;
    const __half* Wp = W + n0;

    auto load_stage = [&](int s, int kt) {
        __half* As = Abase + s * ASTAGE;
        __half* Bs = Bbase + s * BSTAGE;
        const __half* Asrc = Ap + kt * BK;
        const __half* Wsrc = Wp + (size_t)kt * BK * ldwc;
        #pragma unroll
        for (int i = 0; i < 2; i++) {
            int idx = tid + i * 256;
            int r = idx >> 2, c8 = idx & 3;
            cp16(As + r * LDA_S + c8 * 8, Asrc + (size_t)r * DD + c8 * 8);
        }
        #pragma unroll
        for (int i = 0; i < 2; i++) {
            int idx = tid + i * 256;
            int r = idx >> 4, c8 = idx & 15;
            cp16(Bs + r * LDB_S + c8 * 8, Wsrc + (size_t)r * ldwc + c8 * 8);
        }
    };

    wmma::fragment<wmma::accumulator, 16, 16, 16, float> acc[2][4];
    #pragma unroll
    for (int i = 0; i < 2; i++)
        #pragma unroll
        for (int j = 0; j < 4; j++)
            wmma::fill_fragment(acc[i][j], 0.0f);

    load_stage(0, 0); CP_COMMIT();
    load_stage(1, 1); CP_COMMIT();
    load_stage(2, 2); CP_COMMIT();

    for (int kt = 0; kt < KITERS; kt++) {
        CP_WAIT2();
        __syncthreads();
        int s = kt & 3;
        const __half* As = Abase + s * ASTAGE;
        const __half* Bs = Bbase + s * BSTAGE;
        #pragma unroll
        for (int kk = 0; kk < BK; kk += 16) {
            wmma::fragment<wmma::matrix_a, 16, 16, 16, __half, wmma::row_major> af[2];
            wmma::fragment<wmma::matrix_b, 16, 16, 16, __half, wmma::row_major> bf[4];
            #pragma unroll
            for (int i = 0; i < 2; i++)
                wmma::load_matrix_sync(af[i], As + (wm * 32 + i * 16) * LDA_S + kk, LDA_S);
            #pragma unroll
            for (int j = 0; j < 4; j++)
                wmma::load_matrix_sync(bf[j], Bs + kk * LDB_S + wn * 64 + j * 16, LDB_S);
            #pragma unroll
            for (int i = 0; i < 2; i++)
                #pragma unroll
                for (int j = 0; j < 4; j++)
                    wmma::mma_sync(acc[i][j], af[i], bf[j], acc[i][j]);
        }
        int kn = kt + 3;
        if (kn < KITERS) load_stage(kn & 3, kn);
        CP_COMMIT();
    }

    #pragma unroll
    for (int i = 0; i < 2; i++)
        #pragma unroll
        for (int j = 0; j < 4; j++)
            wmma::store_matrix_sync(
                C + (size_t)(m0 + wm * 32 + i * 16) * ldwc + n0 + wn * 64 + j * 16,
                acc[i][j], ldwc, wmma::mem_row_major);
}

// ---------------- complex gate helper ----------------
__device__ __forceinline__ void make_ac(float ar, float ai, float& acr, float& aci) {
    float r = sqrtf(ar * ar + ai * ai);
    float s = 1.0f / (1.0f + __expf(-r));
    if (r > 0.0f) {
        float inv = s / r;
        acr = ar * inv;
        aci = ai * inv;
    } else {
        acr = s;
        aci = 0.0f;
    }
}

// ---------------- scan pass 1: per-chunk summaries (float4, 4 ch/thread) ----------------
__global__ void __launch_bounds__(256) scan_pass1() {
    int d4 = threadIdx.x;          // float4 index: channels 4*d4 .. 4*d4+3
    int c = blockIdx.y;
    int b = blockIdx.z;
    const float* bse = g_proj + (size_t)(b * SS + c * CLEN) * NPROJ;
    float Ar[4] = {1.f,1.f,1.f,1.f}, Ai[4] = {0,0,0,0};
    float Hr[4] = {0,0,0,0}, Hi[4] = {0,0,0,0};
    #pragma unroll 2
    for (int t = 0; t < CLEN; t++) {
        const float* row = bse + (size_t)t * NPROJ;
        float4 ar = ((const float4*)(row + OFF_AR))[d4];
        float4 ai = ((const float4*)(row + OFF_AI))[d4];
        float4 k  = ((const float4*)(row + OFF_K ))[d4];
        float4 v  = ((const float4*)(row + OFF_V ))[d4];
        float arr[4] = {ar.x, ar.y, ar.z, ar.w};
        float aii[4] = {ai.x, ai.y, ai.z, ai.w};
        float kk_[4] = {k.x, k.y, k.z, k.w};
        float vv_[4] = {v.x, v.y, v.z, v.w};
        #pragma unroll
        for (int l = 0; l < 4; l++) {
            float acr, aci;
            make_ac(arr[l], aii[l], acr, aci);
            float kv = kk_[l] * vv_[l];
            float nHr = acr * Hr[l] - aci * Hi[l] + kv;
            float nHi = acr * Hi[l] + aci * Hr[l];
            Hr[l] = nHr; Hi[l] = nHi;
            float nAr = acr * Ar[l] - aci * Ai[l];
            float nAi = acr * Ai[l] + aci * Ar[l];
            Ar[l] = nAr; Ai[l] = nAi;
        }
    }
    size_t o4 = ((size_t)(b * CHUNKS + c) * DD) / 4 + d4;
    ((float4*)g_cAr)[o4] = make_float4(Ar[0], Ar[1], Ar[2], Ar[3]);
    ((float4*)g_cAi)[o4] = make_float4(Ai[0], Ai[1], Ai[2], Ai[3]);
    ((float4*)g_cHr)[o4] = make_float4(Hr[0], Hr[1], Hr[2], Hr[3]);
    ((float4*)g_cHi)[o4] = make_float4(Hi[0], Hi[1], Hi[2], Hi[3]);
}

// ---------------- scan pass 2 (float4, 4 ch/thread) ----------------
__global__ void __launch_bounds__(256) scan_pass2() {
    int b = blockIdx.x;
    int d4 = threadIdx.x;
    float hr[4] = {0,0,0,0}, hi[4] = {0,0,0,0};
    for (int c = 0; c < CHUNKS; c++) {
        size_t o4 = ((size_t)(b * CHUNKS + c) * DD) / 4 + d4;
        ((float4*)g_hinr)[o4] = make_float4(hr[0], hr[1], hr[2], hr[3]);
        ((float4*)g_hini)[o4] = make_float4(hi[0], hi[1], hi[2], hi[3]);
        float4 Ar = ((const float4*)g_cAr)[o4];
        float4 Ai = ((const float4*)g_cAi)[o4];
        float4 Hr = ((const float4*)g_cHr)[o4];
        float4 Hi = ((const float4*)g_cHi)[o4];
        float Arr[4] = {Ar.x, Ar.y, Ar.z, Ar.w};
        float Aii[4] = {Ai.x, Ai.y, Ai.z, Ai.w};
        float Hrr[4] = {Hr.x, Hr.y, Hr.z, Hr.w};
        float Hii[4] = {Hi.x, Hi.y, Hi.z, Hi.w};
        #pragma unroll
        for (int l = 0; l < 4; l++) {
            float nr = Arr[l] * hr[l] - Aii[l] * hi[l] + Hrr[l];
            float ni = Arr[l] * hi[l] + Aii[l] * hr[l] + Hii[l];
            hr[l] = nr; hi[l] = ni;
        }
    }
}

// ---------------- scan pass 3: replay + gates -> g_yh (float4 in, half4 out) ----------------
__global__ void __launch_bounds__(256) scan_pass3() {
    int d4 = threadIdx.x;
    int c = blockIdx.y;
    int b = blockIdx.z;
    size_t o4 = ((size_t)(b * CHUNKS + c) * DD) / 4 + d4;
    float4 h0r = ((const float4*)g_hinr)[o4];
    float4 h0i = ((const float4*)g_hini)[o4];
    float hr[4] = {h0r.x, h0r.y, h0r.z, h0r.w};
    float hi[4] = {h0i.x, h0i.y, h0i.z, h0i.w};
    const float* bse = g_proj + (size_t)(b * SS + c * CLEN) * NPROJ;
    __half* ybase = g_yh + (size_t)(b * SS + c * CLEN) * DD;
    #pragma unroll 2
    for (int t = 0; t < CLEN; t++) {
        const float* row = bse + (size_t)t * NPROJ;
        float4 ar = ((const float4*)(row + OFF_AR))[d4];
        float4 ai = ((const float4*)(row + OFF_AI))[d4];
        float4 k  = ((const float4*)(row + OFF_K ))[d4];
        float4 v  = ((const float4*)(row + OFF_V ))[d4];
        float4 q  = ((const float4*)(row + OFF_Q ))[d4];
        float4 g  = ((const float4*)(row + OFF_G ))[d4];
        float arr[4] = {ar.x, ar.y, ar.z, ar.w};
        float aii[4] = {ai.x, ai.y, ai.z, ai.w};
        float kk_[4] = {k.x, k.y, k.z, k.w};
        float vv_[4] = {v.x, v.y, v.z, v.w};
        float qq_[4] = {q.x, q.y, q.z, q.w};
        float gg_[4] = {g.x, g.y, g.z, g.w};
        float yv[4];
        #pragma unroll
        for (int l = 0; l < 4; l++) {
            float acr, aci;
            make_ac(arr[l], aii[l], acr, aci);
            float kv = kk_[l] * vv_[l];
            float nhr = acr * hr[l] - aci * hi[l] + kv;
            float nhi = acr * hi[l] + aci * hr[l];
            hr[l] = nhr; hi[l] = nhi;
            float silu = gg_[l] / (1.0f + __expf(-gg_[l]));
            yv[l] = qq_[l] * nhr * silu;
        }
        *(uint2*)(ybase + (size_t)t * DD + d4 * 4) =
            f4_to_h4(make_float4(yv[0], yv[1], yv[2], yv[3]));
    }
}

// ---------------- launcher ----------------
extern "C" void kernel_launch(void* const* d_in, const int* in_sizes, int n_in,
                              void* d_out, int out_size) {
    const float* x  = (const float*)d_in[0];
    const float* wq = (const float*)d_in[1];
    const float* wk = (const float*)d_in[2];
    const float* wv = (const float*)d_in[3];
    const float* wa = (const float*)d_in[4];
    const float* wg = (const float*)d_in[5];
    const float* wo = (const float*)d_in[6];
    const float* rs = (const float*)d_in[7];
    float* out = (float*)d_out;

    __half *xnh, *yh, *wr, *wro;
    float *proj;
    cudaGetSymbolAddress((void**)&xnh, g_xnh);
    cudaGetSymbolAddress((void**)&proj, g_proj);
    cudaGetSymbolAddress((void**)&yh,  g_yh);
    cudaGetSymbolAddress((void**)&wr,  g_wr);
    cudaGetSymbolAddress((void**)&wro, g_wro);

    cudaFuncSetAttribute(gemm_fp16, cudaFuncAttributeMaxDynamicSharedMemorySize, SMEM_BYTES);

    // Launches 1-3; projection GEMM is my launch #4 (5th overall with the
    // harness pre-launch -> captured by ncu -s 5 -c 1)
    rmsnorm_kernel<<<MROWS, 256>>>(x, rs);                                   // 1
    w3_to_half<<<1024, 256>>>((const float4*)wq, (const float4*)wk,
                              (const float4*)wv);                            // 2
    wrest_to_half<<<4096, 256>>>((const float4*)wa, (const float4*)wg,
                                 (const float4*)wo);                         // 3

    // 4. Fused projection GEMM: [16384,1024] @ [1024,6144] (fp16 in, fp32 out)
    gemm_fp16<<<dim3(NPROJ / BN, MROWS / BM), 256, SMEM_BYTES>>>(xnh, wr, proj, NPROJ);

    // 5-7. Chunked associative scan + gating (vectorized: 4 channels/thread)
    dim3 gs(1, CHUNKS, BB);
    scan_pass1<<<gs, 256>>>();
    scan_pass2<<<BB, 256>>>();
    scan_pass3<<<gs, 256>>>();

    // 8. Output projection: [16384,1024] @ [1024,1024]
    gemm_fp16<<<dim3(DD / BN, MROWS / BM), 256, SMEM_BYTES>>>(yh, wro, out, DD);
}

// round 16
// speedup vs baseline: 1.0414x; 1.0414x over previous
#include <cuda_runtime.h>
#include <cuda_fp16.h>
#include <mma.h>
#include <cstdint>

using namespace nvcuda;

// ---------------- problem constants ----------------
#define BB 4
#define SS 4096
#define DD 1024
#define MROWS (BB*SS)        // 16384
#define NPROJ 6144           // q|k|v|ar|ai|g
#define CHUNKS 128
#define CLEN 32              // SS / CHUNKS
#define EPS 1e-6f

#define OFF_Q  0
#define OFF_K  1024
#define OFF_V  2048
#define OFF_AR 3072
#define OFF_AI 4096
#define OFF_G  5120

// ---------------- GEMM tiling (fp16 operands, fp32 accum) ----------------
#define BM 128
#define BN 128
#define BK 32                // halfs per K chunk
#define KITERS (DD/BK)       // 32
#define LDA_S 40             // padded A row stride (halfs)
#define LDB_S 136            // padded B row stride (halfs)
#define ASTAGE (BM*LDA_S)    // 5120 halfs
#define BSTAGE (BK*LDB_S)    // 4352 halfs
#define NSTAGE 4
#define SMEM_BYTES (NSTAGE*(ASTAGE+BSTAGE)*2)   // 75776 B

// ---------------- scratch (device globals) ----------------
__device__ __half g_xnh[(size_t)MROWS * DD];      // 32 MB
__device__ float  g_proj[(size_t)MROWS * NPROJ];  // 384 MB
__device__ __half g_yh[(size_t)MROWS * DD];       // 32 MB
__device__ __half g_wr[(size_t)DD * NPROJ];       // fused weights fp16 [1024,6144]
__device__ __half g_wro[(size_t)DD * DD];
__device__ float g_cAr[BB * CHUNKS * DD];
__device__ float g_cAi[BB * CHUNKS * DD];
__device__ float g_cHr[BB * CHUNKS * DD];
__device__ float g_cHi[BB * CHUNKS * DD];
__device__ float g_hinr[BB * CHUNKS * DD];
__device__ float g_hini[BB * CHUNKS * DD];

// ---------------- helpers ----------------
__device__ __forceinline__ uint32_t smem_u32(const void* p) {
    uint32_t a;
    asm("{ .reg .u64 t; cvta.to.shared.u64 t, %1; cvt.u32.u64 %0, t; }" : "=r"(a) : "l"(p));
    return a;
}
__device__ __forceinline__ void cp16(void* dst, const void* src) {
    uint32_t d = smem_u32(dst);
    asm volatile("cp.async.cg.shared.global [%0], [%1], 16;" :: "r"(d), "l"(src));
}
#define CP_COMMIT() asm volatile("cp.async.commit_group;" ::: "memory")
#define CP_WAIT2()  asm volatile("cp.async.wait_group 2;" ::: "memory")

__device__ __forceinline__ uint2 f4_to_h4(float4 v) {
    __half2 lo = __floats2half2_rn(v.x, v.y);
    __half2 hi = __floats2half2_rn(v.z, v.w);
    uint2 r;
    r.x = *(uint32_t*)&lo;
    r.y = *(uint32_t*)&hi;
    return r;
}

// ---------------- RMSNorm: x -> g_xnh (half) ----------------
__global__ void __launch_bounds__(256) rmsnorm_kernel(const float* __restrict__ x,
                                                      const float* __restrict__ scale) {
    int row = blockIdx.x;
    int tid = threadIdx.x;
    const float4* xr = (const float4*)(x + (size_t)row * DD);
    float4 v = xr[tid];
    float ss = v.x * v.x + v.y * v.y + v.z * v.z + v.w * v.w;
    #pragma unroll
    for (int o = 16; o; o >>= 1) ss += __shfl_xor_sync(0xffffffffu, ss, o);
    __shared__ float sbuf[8];
    if ((tid & 31) == 0) sbuf[tid >> 5] = ss;
    __syncthreads();
    if (tid < 8) {
        float t = sbuf[tid];
        #pragma unroll
        for (int o = 4; o; o >>= 1) t += __shfl_xor_sync(0xffu, t, o);
        if (tid == 0) sbuf[0] = t;
    }
    __syncthreads();
    float inv = rsqrtf(sbuf[0] * (1.0f / DD) + EPS);
    float4 sc = ((const float4*)scale)[tid];
    float4 o;
    o.x = v.x * inv * sc.x;
    o.y = v.y * inv * sc.y;
    o.z = v.z * inv * sc.z;
    o.w = v.w * inv * sc.w;
    *(uint2*)(g_xnh + (size_t)row * DD + tid * 4) = f4_to_h4(o);
}

// ---------------- weight converts ----------------
__global__ void __launch_bounds__(256) w3_to_half(const float4* __restrict__ q,
                                                  const float4* __restrict__ k,
                                                  const float4* __restrict__ v) {
    int row = blockIdx.x;
    int tid = threadIdx.x;
    const float4* srcs[3] = { q, k, v };
    #pragma unroll
    for (int m = 0; m < 3; m++) {
        float4 val = srcs[m][(size_t)row * 256 + tid];
        *(uint2*)(g_wr + (size_t)row * NPROJ + m * 1024 + tid * 4) = f4_to_h4(val);
    }
}
__global__ void __launch_bounds__(256) wrest_to_half(const float4* __restrict__ wa,
                                                     const float4* __restrict__ wg,
                                                     const float4* __restrict__ wo) {
    int bid = blockIdx.x;
    int tid = threadIdx.x;
    if (bid < 2048) {               // wa: 1024 rows x 512 f4
        int k = bid >> 1;
        int c = (bid & 1) * 256 + tid;
        float4 v = wa[(size_t)k * 512 + c];
        *(uint2*)(g_wr + (size_t)k * NPROJ + 3072 + c * 4) = f4_to_h4(v);
    } else if (bid < 3072) {        // wg
        int k = bid - 2048;
        float4 v = wg[(size_t)k * 256 + tid];
        *(uint2*)(g_wr + (size_t)k * NPROJ + 5120 + tid * 4) = f4_to_h4(v);
    } else {                        // wo
        int k = bid - 3072;
        float4 v = wo[(size_t)k * 256 + tid];
        *(uint2*)(g_wro + (size_t)k * DD + tid * 4) = f4_to_h4(v);
    }
}

// ---------------- fp16 GEMM (256 thr, 4x2 warps, 4-stage cp.async) ----------------
__global__ void __launch_bounds__(256, 2) gemm_fp16(const __half* __restrict__ A,
                                                    const __half* __restrict__ W,
                                                    float* __restrict__ C, int ldwc) {
    extern __shared__ __half sm[];
    __half* Abase = sm;
    __half* Bbase = sm + NSTAGE * ASTAGE;

    int tid = threadIdx.x;
    int wid = tid >> 5;
    int wm = wid & 3;            // 4 warps along M (32 rows each)
    int wn = wid >> 2;           // 2 warps along N (64 cols each)
    int m0 = blockIdx.y * BM;
    int n0 = blockIdx.x * BN;

    const __half* Ap = A + (size_t)m0 * DD;
    const __half* Wp = W + n0;

    auto load_stage = [&](int s, int kt) {
        __half* As = Abase + s * ASTAGE;
        __half* Bs = Bbase + s * BSTAGE;
        const __half* Asrc = Ap + kt * BK;
        const __half* Wsrc = Wp + (size_t)kt * BK * ldwc;
        #pragma unroll
        for (int i = 0; i < 2; i++) {
            int idx = tid + i * 256;
            int r = idx >> 2, c8 = idx & 3;
            cp16(As + r * LDA_S + c8 * 8, Asrc + (size_t)r * DD + c8 * 8);
        }
        #pragma unroll
        for (int i = 0; i < 2; i++) {
            int idx = tid + i * 256;
            int r = idx >> 4, c8 = idx & 15;
            cp16(Bs + r * LDB_S + c8 * 8, Wsrc + (size_t)r * ldwc + c8 * 8);
        }
    };

    wmma::fragment<wmma::accumulator, 16, 16, 16, float> acc[2][4];
    #pragma unroll
    for (int i = 0; i < 2; i++)
        #pragma unroll
        for (int j = 0; j < 4; j++)
            wmma::fill_fragment(acc[i][j], 0.0f);

    load_stage(0, 0); CP_COMMIT();
    load_stage(1, 1); CP_COMMIT();
    load_stage(2, 2); CP_COMMIT();

    for (int kt = 0; kt < KITERS; kt++) {
        CP_WAIT2();
        __syncthreads();
        int s = kt & 3;
        const __half* As = Abase + s * ASTAGE;
        const __half* Bs = Bbase + s * BSTAGE;
        #pragma unroll
        for (int kk = 0; kk < BK; kk += 16) {
            wmma::fragment<wmma::matrix_a, 16, 16, 16, __half, wmma::row_major> af[2];
            wmma::fragment<wmma::matrix_b, 16, 16, 16, __half, wmma::row_major> bf[4];
            #pragma unroll
            for (int i = 0; i < 2; i++)
                wmma::load_matrix_sync(af[i], As + (wm * 32 + i * 16) * LDA_S + kk, LDA_S);
            #pragma unroll
            for (int j = 0; j < 4; j++)
                wmma::load_matrix_sync(bf[j], Bs + kk * LDB_S + wn * 64 + j * 16, LDB_S);
            #pragma unroll
            for (int i = 0; i < 2; i++)
                #pragma unroll
                for (int j = 0; j < 4; j++)
                    wmma::mma_sync(acc[i][j], af[i], bf[j], acc[i][j]);
        }
        int kn = kt + 3;
        if (kn < KITERS) load_stage(kn & 3, kn);
        CP_COMMIT();
    }

    #pragma unroll
    for (int i = 0; i < 2; i++)
        #pragma unroll
        for (int j = 0; j < 4; j++)
            wmma::store_matrix_sync(
                C + (size_t)(m0 + wm * 32 + i * 16) * ldwc + n0 + wn * 64 + j * 16,
                acc[i][j], ldwc, wmma::mem_row_major);
}

// ---------------- complex gate helper ----------------
__device__ __forceinline__ void make_ac(float ar, float ai, float& acr, float& aci) {
    float r = sqrtf(ar * ar + ai * ai);
    float s = 1.0f / (1.0f + __expf(-r));
    if (r > 0.0f) {
        float inv = s / r;
        acr = ar * inv;
        aci = ai * inv;
    } else {
        acr = s;
        aci = 0.0f;
    }
}

// ---------------- scan pass 1: per-chunk summaries (float4, 4 ch/thread, 512 CTAs) ----------------
__global__ void __launch_bounds__(256) scan_pass1() {
    int d4 = threadIdx.x;          // float4 index: channels 4*d4 .. 4*d4+3
    int c = blockIdx.y;
    int b = blockIdx.z;
    const float* bse = g_proj + (size_t)(b * SS + c * CLEN) * NPROJ;
    float Ar[4] = {1.f,1.f,1.f,1.f}, Ai[4] = {0,0,0,0};
    float Hr[4] = {0,0,0,0}, Hi[4] = {0,0,0,0};
    #pragma unroll 2
    for (int t = 0; t < CLEN; t++) {
        const float* row = bse + (size_t)t * NPROJ;
        float4 ar = ((const float4*)(row + OFF_AR))[d4];
        float4 ai = ((const float4*)(row + OFF_AI))[d4];
        float4 k  = ((const float4*)(row + OFF_K ))[d4];
        float4 v  = ((const float4*)(row + OFF_V ))[d4];
        float arr[4] = {ar.x, ar.y, ar.z, ar.w};
        float aii[4] = {ai.x, ai.y, ai.z, ai.w};
        float kk_[4] = {k.x, k.y, k.z, k.w};
        float vv_[4] = {v.x, v.y, v.z, v.w};
        #pragma unroll
        for (int l = 0; l < 4; l++) {
            float acr, aci;
            make_ac(arr[l], aii[l], acr, aci);
            float kv = kk_[l] * vv_[l];
            float nHr = acr * Hr[l] - aci * Hi[l] + kv;
            float nHi = acr * Hi[l] + aci * Hr[l];
            Hr[l] = nHr; Hi[l] = nHi;
            float nAr = acr * Ar[l] - aci * Ai[l];
            float nAi = acr * Ai[l] + aci * Ar[l];
            Ar[l] = nAr; Ai[l] = nAi;
        }
    }
    size_t o4 = ((size_t)(b * CHUNKS + c) * DD) / 4 + d4;
    ((float4*)g_cAr)[o4] = make_float4(Ar[0], Ar[1], Ar[2], Ar[3]);
    ((float4*)g_cAi)[o4] = make_float4(Ai[0], Ai[1], Ai[2], Ai[3]);
    ((float4*)g_cHr)[o4] = make_float4(Hr[0], Hr[1], Hr[2], Hr[3]);
    ((float4*)g_cHi)[o4] = make_float4(Hi[0], Hi[1], Hi[2], Hi[3]);
}

// ---------------- scan pass 2 (float4, 4 ch/thread, L2-resident) ----------------
__global__ void __launch_bounds__(256) scan_pass2() {
    int b = blockIdx.x;
    int d4 = threadIdx.x;
    float hr[4] = {0,0,0,0}, hi[4] = {0,0,0,0};
    for (int c = 0; c < CHUNKS; c++) {
        size_t o4 = ((size_t)(b * CHUNKS + c) * DD) / 4 + d4;
        ((float4*)g_hinr)[o4] = make_float4(hr[0], hr[1], hr[2], hr[3]);
        ((float4*)g_hini)[o4] = make_float4(hi[0], hi[1], hi[2], hi[3]);
        float4 Ar = ((const float4*)g_cAr)[o4];
        float4 Ai = ((const float4*)g_cAi)[o4];
        float4 Hr = ((const float4*)g_cHr)[o4];
        float4 Hi = ((const float4*)g_cHi)[o4];
        float Arr[4] = {Ar.x, Ar.y, Ar.z, Ar.w};
        float Aii[4] = {Ai.x, Ai.y, Ai.z, Ai.w};
        float Hrr[4] = {Hr.x, Hr.y, Hr.z, Hr.w};
        float Hii[4] = {Hi.x, Hi.y, Hi.z, Hi.w};
        #pragma unroll
        for (int l = 0; l < 4; l++) {
            float nr = Arr[l] * hr[l] - Aii[l] * hi[l] + Hrr[l];
            float ni = Arr[l] * hi[l] + Aii[l] * hr[l] + Hii[l];
            hr[l] = nr; hi[l] = ni;
        }
    }
}

// ---------------- scan pass 3: replay + gates -> g_yh (float4 in, half4 out) ----------------
__global__ void __launch_bounds__(256) scan_pass3() {
    int d4 = threadIdx.x;
    int c = blockIdx.y;
    int b = blockIdx.z;
    size_t o4 = ((size_t)(b * CHUNKS + c) * DD) / 4 + d4;
    float4 h0r = ((const float4*)g_hinr)[o4];
    float4 h0i = ((const float4*)g_hini)[o4];
    float hr[4] = {h0r.x, h0r.y, h0r.z, h0r.w};
    float hi[4] = {h0i.x, h0i.y, h0i.z, h0i.w};
    const float* bse = g_proj + (size_t)(b * SS + c * CLEN) * NPROJ;
    __half* ybase = g_yh + (size_t)(b * SS + c * CLEN) * DD;
    #pragma unroll 2
    for (int t = 0; t < CLEN; t++) {
        const float* row = bse + (size_t)t * NPROJ;
        float4 ar = ((const float4*)(row + OFF_AR))[d4];
        float4 ai = ((const float4*)(row + OFF_AI))[d4];
        float4 k  = ((const float4*)(row + OFF_K ))[d4];
        float4 v  = ((const float4*)(row + OFF_V ))[d4];
        float4 q  = ((const float4*)(row + OFF_Q ))[d4];
        float4 g  = ((const float4*)(row + OFF_G ))[d4];
        float arr[4] = {ar.x, ar.y, ar.z, ar.w};
        float aii[4] = {ai.x, ai.y, ai.z, ai.w};
        float kk_[4] = {k.x, k.y, k.z, k.w};
        float vv_[4] = {v.x, v.y, v.z, v.w};
        float qq_[4] = {q.x, q.y, q.z, q.w};
        float gg_[4] = {g.x, g.y, g.z, g.w};
        float yv[4];
        #pragma unroll
        for (int l = 0; l < 4; l++) {
            float acr, aci;
            make_ac(arr[l], aii[l], acr, aci);
            float kv = kk_[l] * vv_[l];
            float nhr = acr * hr[l] - aci * hi[l] + kv;
            float nhi = acr * hi[l] + aci * hr[l];
            hr[l] = nhr; hi[l] = nhi;
            float silu = gg_[l] / (1.0f + __expf(-gg_[l]));
            yv[l] = qq_[l] * nhr * silu;
        }
        *(uint2*)(ybase + (size_t)t * DD + d4 * 4) =
            f4_to_h4(make_float4(yv[0], yv[1], yv[2], yv[3]));
    }
}

// ---------------- launcher ----------------
extern "C" void kernel_launch(void* const* d_in, const int* in_sizes, int n_in,
                              void* d_out, int out_size) {
    const float* x  = (const float*)d_in[0];
    const float* wq = (const float*)d_in[1];
    const float* wk = (const float*)d_in[2];
    const float* wv = (const float*)d_in[3];
    const float* wa = (const float*)d_in[4];
    const float* wg = (const float*)d_in[5];
    const float* wo = (const float*)d_in[6];
    const float* rs = (const float*)d_in[7];
    float* out = (float*)d_out;

    __half *xnh, *yh, *wr, *wro;
    float *proj;
    cudaGetSymbolAddress((void**)&xnh, g_xnh);
    cudaGetSymbolAddress((void**)&proj, g_proj);
    cudaGetSymbolAddress((void**)&yh,  g_yh);
    cudaGetSymbolAddress((void**)&wr,  g_wr);
    cudaGetSymbolAddress((void**)&wro, g_wro);

    cudaFuncSetAttribute(gemm_fp16, cudaFuncAttributeMaxDynamicSharedMemorySize, SMEM_BYTES);

    // Launches 1-3; projection GEMM is my launch #4 (5th overall with the
    // harness pre-launch -> captured by ncu -s 5 -c 1)
    rmsnorm_kernel<<<MROWS, 256>>>(x, rs);                                   // 1
    w3_to_half<<<1024, 256>>>((const float4*)wq, (const float4*)wk,
                              (const float4*)wv);                            // 2
    wrest_to_half<<<4096, 256>>>((const float4*)wa, (const float4*)wg,
                                 (const float4*)wo);                         // 3

    // 4. Fused projection GEMM: [16384,1024] @ [1024,6144] (fp16 in, fp32 out)
    gemm_fp16<<<dim3(NPROJ / BN, MROWS / BM), 256, SMEM_BYTES>>>(xnh, wr, proj, NPROJ);

    // 5-7. Chunked associative scan + gating (float4, 512 CTAs for pass1/pass3)
    dim3 gs(1, CHUNKS, BB);
    scan_pass1<<<gs, 256>>>();
    scan_pass2<<<BB, 256>>>();
    scan_pass3<<<gs, 256>>>();

    // 8. Output projection: [16384,1024] @ [1024,1024]
    gemm_fp16<<<dim3(DD / BN, MROWS / BM), 256, SMEM_BYTES>>>(yh, wro, out, DD);
}